// round 6
// baseline (speedup 1.0000x reference)
#include <cuda_runtime.h>
#include <cuda_bf16.h>
#include <cstddef>

// Problem constants (fixed by the dataset)
#define BATCH 64
#define LSEQ  512
#define DIN   256
#define HDIM  256
#define H3    768
#define ADIM  128
#define DEPTH 4
#define NROWS (LSEQ * BATCH)   // 32768
#define NCAT  896              // 768 xp + 128 xa

#define CLUSTER_NCTAS 8
#define ROWS_PER_CTA  112
#define NBAT          4
#define NCLU          16
#define SCAN_THREADS  896
#define RECA          1824     // floats per rank: 448 rows x4 + 8 stats (+pad)
#define RECH          160      // floats per rank: 128 h + 4 logit partials (+pad)
#define CLUSPAN       16384    // floats per cluster in g_hp

// SMEM weight layout: row r = 72 float4 (8 kq-blocks of 9: 8 data + 1 pad)
#define WROW_F4  72
// hT layout: float4 per k (4 batches), 33-f4 blocks (32 data + 1 pad)
#define HT_F4(k)        ((((k) >> 5) * 33) + ((k) & 31))
#define HT_FLT(k, b)    ((((k) >> 5) * 132) + (((k) & 31) * 4) + (b))

// ---------------- scratch (device globals; no allocation allowed) -------------
__device__ float g_hseq[(size_t)NROWS * HDIM];
__device__ float g_xpa [(size_t)NROWS * NCAT];
__device__ float g_Wcat[(size_t)DIN * NCAT];
__device__ float g_Ut2 [(size_t)(H3 + ADIM) * HDIM];
__device__ float g_hp  [(size_t)NCLU * CLUSPAN];
__device__ unsigned char g_mask[BATCH * LSEQ];

// ---------------------------------- helpers ----------------------------------
__device__ __forceinline__ float warp_sum(float v) {
#pragma unroll
    for (int o = 16; o > 0; o >>= 1) v += __shfl_down_sync(0xffffffffu, v, o);
    return v;
}
__device__ __forceinline__ float sigmoidf(float x) { return 1.0f / (1.0f + expf(-x)); }

__device__ __forceinline__ void fma2(unsigned long long& d, unsigned long long a,
                                     unsigned long long b) {
    asm("fma.rn.f32x2 %0, %1, %2, %0;" : "+l"(d) : "l"(a), "l"(b));
}
__device__ __forceinline__ unsigned long long pk(float lo, float hi) {
    unsigned long long r;
    asm("mov.b64 %0, {%1, %2};" : "=l"(r) : "f"(lo), "f"(hi));
    return r;
}
__device__ __forceinline__ float2 upk(unsigned long long v) {
    float2 r;
    asm("mov.b64 {%0, %1}, %2;" : "=f"(r.x), "=f"(r.y) : "l"(v));
    return r;
}

// ----------------- fused prep: Ut2 transpose + Wcat + mask --------------------
__global__ void prep_fused(const float* __restrict__ U, const float* __restrict__ Ua1,
                           const float* __restrict__ W, const float* __restrict__ Wa1,
                           const unsigned char* __restrict__ m8) {
    int k = blockIdx.x;
    if (k < H3 + ADIM) {
        int i = threadIdx.x;
        float v = (k < H3) ? U[(size_t)i * H3 + k] : Ua1[(size_t)i * ADIM + (k - H3)];
        g_Ut2[(size_t)k * HDIM + i] = v;
    } else if (k < H3 + ADIM + DIN) {
        int r = k - (H3 + ADIM);
        for (int n = threadIdx.x; n < NCAT; n += blockDim.x)
            g_Wcat[(size_t)r * NCAT + n] =
                (n < H3) ? W[(size_t)r * H3 + n] : Wa1[(size_t)r * ADIM + (n - H3)];
    } else {
        __shared__ int mode;
        if (threadIdx.x == 0) {
            int nz = 0;
            for (int i = 0; i < 64; i++) nz |= m8[4 * i + 1] | m8[4 * i + 2] | m8[4 * i + 3];
            mode = nz ? 1 : 0;
        }
        __syncthreads();
        if (mode) {
            for (int i = threadIdx.x; i < BATCH * LSEQ; i += blockDim.x)
                g_mask[i] = m8[i] ? 1 : 0;
        } else {
            const int* m32 = (const int*)m8;
            for (int i = threadIdx.x; i < BATCH * LSEQ; i += blockDim.x)
                g_mask[i] = m32[i] ? 1 : 0;
        }
    }
}

// ------------------------------- tiled SGEMM (f32x2) --------------------------
template <bool REMAP>
__global__ void __launch_bounds__(256) sgemm_kernel(
    const float* __restrict__ A, const float* __restrict__ Bm,
    const float* __restrict__ bias, float* __restrict__ C, int N) {
    const int K = 256;
    __shared__ __align__(16) float Ast[16][68];
    __shared__ __align__(16) float Bs[16][64];
    int t  = threadIdx.x;
    int m0 = blockIdx.y * 64;
    int n0 = blockIdx.x * 64;
    int ty = t >> 4, tx = t & 15;

    unsigned long long acc2[4][2];
#pragma unroll
    for (int i = 0; i < 4; i++) { acc2[i][0] = 0ull; acc2[i][1] = 0ull; }

    int ar = t >> 2;
    int ak = (t & 3) * 4;
    int arow = m0 + ar;
    const float* Aptr;
    if (REMAP) {
        int b = arow & 63, l = arow >> 6;
        Aptr = A + ((size_t)b * LSEQ + l) * K;
    } else {
        Aptr = A + (size_t)arow * K;
    }
    int bk = t >> 4;
    int bn = (t & 15) * 4;

    for (int k0 = 0; k0 < K; k0 += 16) {
        float4 av = *(const float4*)(Aptr + k0 + ak);
        Ast[ak + 0][ar] = av.x;
        Ast[ak + 1][ar] = av.y;
        Ast[ak + 2][ar] = av.z;
        Ast[ak + 3][ar] = av.w;
        *(float4*)(&Bs[bk][bn]) = *(const float4*)(Bm + (size_t)(k0 + bk) * N + n0 + bn);
        __syncthreads();
#pragma unroll
        for (int kk = 0; kk < 16; kk++) {
            float4 a  = *(const float4*)(&Ast[kk][ty * 4]);
            float4 bb = *(const float4*)(&Bs[kk][tx * 4]);
            unsigned long long b01 = pk(bb.x, bb.y), b23 = pk(bb.z, bb.w);
            unsigned long long ax = pk(a.x, a.x), ay = pk(a.y, a.y);
            unsigned long long az = pk(a.z, a.z), aw = pk(a.w, a.w);
            fma2(acc2[0][0], ax, b01); fma2(acc2[0][1], ax, b23);
            fma2(acc2[1][0], ay, b01); fma2(acc2[1][1], ay, b23);
            fma2(acc2[2][0], az, b01); fma2(acc2[2][1], az, b23);
            fma2(acc2[3][0], aw, b01); fma2(acc2[3][1], aw, b23);
        }
        __syncthreads();
    }
#pragma unroll
    for (int i = 0; i < 4; i++) {
        int row = m0 + ty * 4 + i;
        float2 v01 = upk(acc2[i][0]), v23 = upk(acc2[i][1]);
        float4 v;
        v.x = v01.x; v.y = v01.y; v.z = v23.x; v.w = v23.y;
        if (bias) {
            v.x += bias[n0 + tx * 4 + 0];
            v.y += bias[n0 + tx * 4 + 1];
            v.z += bias[n0 + tx * 4 + 2];
            v.w += bias[n0 + tx * 4 + 3];
        }
        *(float4*)(&C[(size_t)row * N + n0 + tx * 4]) = v;
    }
}

// --------------------- cluster-resident scan, distributed phase B -------------
// rank r = 2*bsel + ch. Phase A: matvec on own 112 weight rows x 4 batches +
// LN partials folded into record. bar1. Phase B: ONLY batch bsel, cols
// [128ch,128ch+128) gates + 64 action-tanh per CTA (8x less MUFU). bar2.
// Gather full h from peers' 128-float records; finalize logits/act/policy.
__global__ void __cluster_dims__(CLUSTER_NCTAS, 1, 1) __launch_bounds__(SCAN_THREADS, 1)
scan3_kernel(int d,
             const float* __restrict__ bg,
             const float* __restrict__ gammas,
             const float* __restrict__ betas,
             const float* __restrict__ ba1,
             const float* __restrict__ Wa2,
             const float* __restrict__ ba2,
             float* __restrict__ out, int out_size) {
    extern __shared__ __align__(16) float sm[];
    float* Wsm   = sm;                                // 112*288 = 32256
    float* s_hT  = Wsm  + ROWS_PER_CTA * WROW_F4 * 4; // 1056
    float* s_xpa = s_hT + 1056;                       // 2*896
    float* c_g0  = s_xpa + 2 * NCAT;                  // 768
    float* c_b0  = c_g0 + H3;
    float* c_g1  = c_b0 + H3;
    float* c_b1  = c_g1 + H3;
    float* c_bg  = c_b1 + H3;
    float* c_ba1 = c_bg + H3;                         // 128
    float* c_wa2 = c_ba1 + ADIM;                      // 256
    float* s_lnA = c_wa2 + 2 * ADIM;                  // 224
    float* s_xscr= s_lnA + 224;                       // 16
    float* s_stat= s_xscr + 16;                       // 2
    float* s_xst = s_stat + 2;                        // 4
    unsigned char* s_mask8 = (unsigned char*)(s_xst + 4); // 512 bytes

    const int t    = threadIdx.x;
    const int rank = blockIdx.x & (CLUSTER_NCTAS - 1);
    const int clu  = blockIdx.x >> 3;
    const int b0   = clu * NBAT;
    const int bsel = rank >> 1, ch = rank & 1;
    const int lane = t & 31, wid = t >> 5;

    // ---- weight slice into padded smem layout ----
    {
        const float4* src = (const float4*)(g_Ut2 + (size_t)(ROWS_PER_CTA * rank) * HDIM);
        float4* dst = (float4*)Wsm;
        for (int i = t; i < ROWS_PER_CTA * 64; i += SCAN_THREADS) {
            int row = i >> 6, c4 = i & 63;
            dst[row * WROW_F4 + (c4 >> 3) * 9 + (c4 & 7)] = src[(size_t)row * 64 + c4];
        }
    }
    for (int i = t; i < H3; i += SCAN_THREADS) {
        c_g0[i] = gammas[i];
        c_b0[i] = betas[i];
        c_g1[i] = gammas[H3 + i];
        c_b1[i] = betas[H3 + i];
        c_bg[i] = bg[i];
    }
    if (t < ADIM)     c_ba1[t] = ba1[t];
    if (t < 2 * ADIM) c_wa2[t] = Wa2[t];
    for (int i = t; i < LSEQ; i += SCAN_THREADS)
        s_mask8[i] = g_mask[(b0 + bsel) * LSEQ + i];
    for (int i = t; i < 1056; i += SCAN_THREADS) s_hT[i] = 0.0f;
    // xpa(0) for own batch
    if (t < 224)
        ((float4*)s_xpa)[t] = *((const float4*)g_xpa + ((size_t)(b0 + bsel)) * 224 + t);
    __syncthreads();
    // xp stats for l=0 (buffer 0)
    if (t < 256) {
        float s = 0.f, q = 0.f;
#pragma unroll
        for (int j = 0; j < 3; j++) { float v = s_xpa[t + 256 * j]; s += v; q += v * v; }
        s = warp_sum(s); q = warp_sum(q);
        if (lane == 0) { s_xscr[wid * 2] = s; s_xscr[wid * 2 + 1] = q; }
    }
    __syncthreads();
    if (t == 0) {
        float S = 0.f, Q = 0.f;
#pragma unroll
        for (int w = 0; w < 8; w++) { S += s_xscr[w * 2]; Q += s_xscr[w * 2 + 1]; }
        float mu = S * (1.0f / 768.0f), var = Q * (1.0f / 768.0f) - mu * mu;
        s_xst[0] = mu; s_xst[1] = rsqrtf(var + 1e-5f);
    }
    __syncthreads();

    const bool write_full = (out_size >= 409600);
    const int r_ = t >> 3, kq = t & 7;
    const float4* wf = (const float4*)Wsm + r_ * WROW_F4 + kq * 9;
    const float4* ht = (const float4*)s_hT;
    const bool lnvalid = (rank * ROWS_PER_CTA + r_) < H3;

    float* gA = g_hp + (size_t)clu * CLUSPAN;
    float* gH = gA + CLUSTER_NCTAS * RECA;
    const float ba2_0 = ba2[0], ba2_1 = ba2[1];

    for (int l = 0; l < LSEQ; ++l) {
        const int par = l & 1, nxt = par ^ 1;

        // ================= phase A: matvec + LN partials =================
        {
            unsigned long long a01 = 0ull, a23 = 0ull;
#pragma unroll
            for (int i = 0; i < 8; i++) {
                float4 w  = wf[i];
                float4 h0 = ht[kq * 33 + i * 4 + 0];
                float4 h1 = ht[kq * 33 + i * 4 + 1];
                float4 h2 = ht[kq * 33 + i * 4 + 2];
                float4 h3 = ht[kq * 33 + i * 4 + 3];
                fma2(a01, pk(w.x, w.x), pk(h0.x, h0.y)); fma2(a23, pk(w.x, w.x), pk(h0.z, h0.w));
                fma2(a01, pk(w.y, w.y), pk(h1.x, h1.y)); fma2(a23, pk(w.y, w.y), pk(h1.z, h1.w));
                fma2(a01, pk(w.z, w.z), pk(h2.x, h2.y)); fma2(a23, pk(w.z, w.z), pk(h2.z, h2.w));
                fma2(a01, pk(w.w, w.w), pk(h3.x, h3.y)); fma2(a23, pk(w.w, w.w), pk(h3.z, h3.w));
            }
            float2 v01 = upk(a01), v23 = upk(a23);
            float d0 = v01.x, d1 = v01.y, d2 = v23.x, d3 = v23.y;
#pragma unroll
            for (int m = 1; m < 8; m <<= 1) {
                d0 += __shfl_xor_sync(0xffffffffu, d0, m);
                d1 += __shfl_xor_sync(0xffffffffu, d1, m);
                d2 += __shfl_xor_sync(0xffffffffu, d2, m);
                d3 += __shfl_xor_sync(0xffffffffu, d3, m);
            }
            if (kq == 0) {
                float4 o; o.x = d0; o.y = d1; o.z = d2; o.w = d3;
                ((float4*)gA)[rank * (RECA / 4) + r_] = o;
            }
            // LN partials over this CTA's rows (<768 only)
            float vs0 = lnvalid ? d0 : 0.f, vs1 = lnvalid ? d1 : 0.f;
            float vs2 = lnvalid ? d2 : 0.f, vs3 = lnvalid ? d3 : 0.f;
            float q0 = vs0 * vs0, q1 = vs1 * vs1, q2 = vs2 * vs2, q3 = vs3 * vs3;
#pragma unroll
            for (int m = 8; m <= 16; m <<= 1) {
                vs0 += __shfl_xor_sync(0xffffffffu, vs0, m);
                vs1 += __shfl_xor_sync(0xffffffffu, vs1, m);
                vs2 += __shfl_xor_sync(0xffffffffu, vs2, m);
                vs3 += __shfl_xor_sync(0xffffffffu, vs3, m);
                q0  += __shfl_xor_sync(0xffffffffu, q0, m);
                q1  += __shfl_xor_sync(0xffffffffu, q1, m);
                q2  += __shfl_xor_sync(0xffffffffu, q2, m);
                q3  += __shfl_xor_sync(0xffffffffu, q3, m);
            }
            if (lane == 0) {
                s_lnA[wid * 8 + 0] = vs0; s_lnA[wid * 8 + 1] = vs1;
                s_lnA[wid * 8 + 2] = vs2; s_lnA[wid * 8 + 3] = vs3;
                s_lnA[wid * 8 + 4] = q0;  s_lnA[wid * 8 + 5] = q1;
                s_lnA[wid * 8 + 6] = q2;  s_lnA[wid * 8 + 7] = q3;
            }
        }
        // prefetch own-batch xpa for l+1 (independent LDG)
        float4 pf;
        const int lp = (l + 1 < LSEQ) ? l + 1 : l;
        if (t >= 512 && t < 736)
            pf = *((const float4*)g_xpa + ((size_t)lp * BATCH + b0 + bsel) * 224 + (t - 512));
        __syncthreads();
        if (t < 8) {
            float acc = 0.f;
#pragma unroll
            for (int w = 0; w < 28; w++) acc += s_lnA[w * 8 + t];
            gA[rank * RECA + 1792 + t] = acc;
        }

        asm volatile("barrier.cluster.arrive.aligned;" ::: "memory");
        asm volatile("barrier.cluster.wait.aligned;" ::: "memory");

        // ================= phase B1: gathers (own slice only) =============
        float hp0r = 0.f, hp1r = 0.f, hp2r = 0.f, hpAr = 0.f, xaval = 0.f;
        int kact = 0;
        if (t < 128) {
            int col = 128 * ch + t;
            int r0 = col, r1 = col + 256, r2 = col + 512;
            hp0r = __ldcv(&gA[(r0 / 112) * RECA + (r0 % 112) * 4 + bsel]);
            hp1r = __ldcv(&gA[(r1 / 112) * RECA + (r1 % 112) * 4 + bsel]);
            hp2r = __ldcv(&gA[(r2 / 112) * RECA + (r2 % 112) * 4 + bsel]);
        } else if (t < 192) {
            kact = 64 * ch + (t - 128);
            int rr = H3 + kact;
            hpAr  = __ldcv(&gA[(rr / 112) * RECA + (rr % 112) * 4 + bsel]);
            xaval = s_xpa[par * NCAT + H3 + kact];
        } else if (t < 224) {
            int i = t - 192;
            float v = 0.f;
            if (i < 16) v = __ldcv(&gA[(i & 7) * RECA + 1792 + (i >> 3) * 4 + bsel]);
            v += __shfl_xor_sync(0xffffffffu, v, 1);
            v += __shfl_xor_sync(0xffffffffu, v, 2);
            v += __shfl_xor_sync(0xffffffffu, v, 4);
            float Q = __shfl_sync(0xffffffffu, v, 8);
            if (i == 0) {
                float mu = v * (1.0f / 768.0f), var = Q * (1.0f / 768.0f) - mu * mu;
                s_stat[0] = mu; s_stat[1] = rsqrtf(var + 1e-5f);
            }
        }
        if (t >= 512 && t < 736) ((float4*)(s_xpa + nxt * NCAT))[t - 512] = pf;
        __syncthreads();

        // ================= phase B2: gates / action / xp-stats ===========
        const unsigned char mt = s_mask8[l];
        if (t < 128) {
            int col = 128 * ch + t;
            float mu = s_stat[0], rs = s_stat[1];
            float mux = s_xst[par * 2], rsx = s_xst[par * 2 + 1];
            const float* xr = s_xpa + par * NCAT;
            float x0 = c_g0[col]       * (xr[col]       - mux) * rsx + c_b0[col];
            float x1 = c_g0[col + 256] * (xr[col + 256] - mux) * rsx + c_b0[col + 256];
            float x2 = c_g0[col + 512] * (xr[col + 512] - mux) * rsx + c_b0[col + 512];
            float hp0 = (hp0r - mu) * rs * c_g1[col]       + c_b1[col];
            float hp1 = (hp1r - mu) * rs * c_g1[col + 256] + c_b1[col + 256];
            float hp2 = (hp2r - mu) * rs * c_g1[col + 512] + c_b1[col + 512];
            float r  = sigmoidf(x0 + hp0     + c_bg[col]);
            float z  = sigmoidf(x1 + hp1     + c_bg[col + 256]);
            float hh = tanhf   (x2 + r * hp2 + c_bg[col + 512]);
            float hold = s_hT[HT_FLT(col, bsel)];
            float hn = z * hold + (1.0f - z) * hh;
            float ho = mt ? hn : hold;
            gH[rank * RECH + t] = ho;
            g_hseq[((size_t)l * BATCH + b0 + bsel) * HDIM + col] = ho;
            if (d == DEPTH - 1 && l == LSEQ - 1 && out_size >= BATCH * HDIM)
                out[(b0 + bsel) * HDIM + col] = ho;
        } else if (t < 192) {
            float a = tanhf(xaval + hpAr + c_ba1[kact]);
            float p0 = warp_sum(a * c_wa2[2 * kact]);
            float p1 = warp_sum(a * c_wa2[2 * kact + 1]);
            if (lane == 0) {
                int wo = (wid - 4) * 2;
                gH[rank * RECH + 128 + wo]     = p0;
                gH[rank * RECH + 129 + wo]     = p1;
            }
        } else if (t >= 512 && t < 768) {
            int u = t - 512;
            const float* xn = s_xpa + nxt * NCAT;
            float s = 0.f, q = 0.f;
#pragma unroll
            for (int j = 0; j < 3; j++) { float v = xn[u + 256 * j]; s += v; q += v * v; }
            s = warp_sum(s); q = warp_sum(q);
            if (lane == 0) { int w = wid - 16; s_xscr[w * 2] = s; s_xscr[w * 2 + 1] = q; }
        }

        asm volatile("barrier.cluster.arrive.aligned;" ::: "memory");
        asm volatile("barrier.cluster.wait.aligned;" ::: "memory");

        // ================= post: h gather / xst / act finalize ===========
        if (t < 256) {
            int k = t;
            float4 o;
            o.x = __ldcv(&gH[(0 + (k >> 7)) * RECH + (k & 127)]);
            o.y = __ldcv(&gH[(2 + (k >> 7)) * RECH + (k & 127)]);
            o.z = __ldcv(&gH[(4 + (k >> 7)) * RECH + (k & 127)]);
            o.w = __ldcv(&gH[(6 + (k >> 7)) * RECH + (k & 127)]);
            ((float4*)s_hT)[HT_F4(k)] = o;
        } else if (t == 256) {
            float S = 0.f, Q = 0.f;
#pragma unroll
            for (int w = 0; w < 8; w++) { S += s_xscr[w * 2]; Q += s_xscr[w * 2 + 1]; }
            float mu = S * (1.0f / 768.0f), var = Q * (1.0f / 768.0f) - mu * mu;
            s_xst[nxt * 2] = mu; s_xst[nxt * 2 + 1] = rsqrtf(var + 1e-5f);
        } else if (t == 288 && ch == 0) {
            float l0 = __ldcv(&gH[rank * RECH + 128]) + __ldcv(&gH[rank * RECH + 130]) +
                       __ldcv(&gH[(rank + 1) * RECH + 128]) + __ldcv(&gH[(rank + 1) * RECH + 130]) + ba2_0;
            float l1 = __ldcv(&gH[rank * RECH + 129]) + __ldcv(&gH[rank * RECH + 131]) +
                       __ldcv(&gH[(rank + 1) * RECH + 129]) + __ldcv(&gH[(rank + 1) * RECH + 131]) + ba2_1;
            int actv = ((l1 > l0) && mt) ? 1 : 0;
            g_mask[(b0 + bsel) * LSEQ + l] = (unsigned char)actv;
            if (write_full) {
                float m = fmaxf(l0, l1);
                float e0 = expf(l0 - m), e1 = expf(l1 - m);
                float inv = 1.0f / (e0 + e1);
                size_t ai = (size_t)BATCH * HDIM + ((size_t)((b0 + bsel) * DEPTH + d)) * LSEQ + l;
                out[ai] = actv ? 1.0f : 0.0f;
                size_t pi = (size_t)BATCH * HDIM + (size_t)BATCH * DEPTH * LSEQ +
                            (((size_t)((b0 + bsel) * DEPTH + d)) * LSEQ + l) * 2;
                out[pi]     = e0 * inv;
                out[pi + 1] = e1 * inv;
            }
        }
        __syncthreads();   // s_hT / s_xst ready for next phase A
    }
}

// --------------------------------- launcher ----------------------------------
extern "C" void kernel_launch(void* const* d_in, const int* in_sizes, int n_in,
                              void* d_out, int out_size) {
    const float* x     = (const float*)d_in[0];
    const unsigned char* mask = (const unsigned char*)d_in[1];
    const float* W_emb = (const float*)d_in[2];
    const float* b_emb = (const float*)d_in[3];
    const float* W     = (const float*)d_in[4];
    const float* U     = (const float*)d_in[5];
    const float* bgate = (const float*)d_in[6];
    const float* Wa1   = (const float*)d_in[7];
    const float* Ua1   = (const float*)d_in[8];
    const float* ba1   = (const float*)d_in[9];
    const float* Wa2   = (const float*)d_in[10];
    const float* ba2   = (const float*)d_in[11];
    const float* gammas = (const float*)d_in[12];
    const float* betas  = (const float*)d_in[13];
    float* out = (float*)d_out;

    float *hseq, *xpa, *wcat;
    cudaGetSymbolAddress((void**)&hseq, g_hseq);
    cudaGetSymbolAddress((void**)&xpa, g_xpa);
    cudaGetSymbolAddress((void**)&wcat, g_Wcat);

    const int scan_smem =
        (ROWS_PER_CTA * WROW_F4 * 4 + 1056 + 2 * NCAT + 5 * H3 + ADIM + 2 * ADIM +
         224 + 16 + 2 + 4) * 4 + LSEQ;
    static int attr_done = 0;
    if (!attr_done) {
        cudaFuncSetAttribute(scan3_kernel, cudaFuncAttributeMaxDynamicSharedMemorySize, scan_smem);
        attr_done = 1;
    }

    prep_fused<<<H3 + ADIM + DIN + 1, HDIM>>>(U, Ua1, W, Wa1, mask);
    sgemm_kernel<true><<<dim3(HDIM / 64, NROWS / 64), 256>>>(x, W_emb, b_emb, hseq, HDIM);

    for (int d = 0; d < DEPTH; d++) {
        sgemm_kernel<false><<<dim3(NCAT / 64, NROWS / 64), 256>>>(hseq, wcat, nullptr, xpa, NCAT);
        scan3_kernel<<<NCLU * CLUSTER_NCTAS, SCAN_THREADS, scan_smem>>>(
            d, bgate, gammas, betas, ba1, Wa2, ba2, out, out_size);
    }
}